// round 1
// baseline (speedup 1.0000x reference)
#include <cuda_runtime.h>
#include <cuda_bf16.h>
#include <math.h>

// Problem constants (capacities; actual n/E read from in_sizes)
#define NMAX   100000
#define FH     64

// Scratch (alloc-free rule: __device__ globals)
__device__ float g_A[NMAX * FH];
__device__ float g_B[NMAX * FH];
__device__ float g_deg[NMAX];
__device__ float g_dinv[NMAX];
__device__ int   g_is64;

// ---------------------------------------------------------------------------
// Probe: detect whether edge_index is int64 or int32.
// Values are in [0, 100000): if int64, every high word of the first 1024
// 8-byte slots is 0. If int32, high words are random edge ids (P(all 0)~0).
__global__ void probe_dtype(const long long* __restrict__ ei) {
    __shared__ int any;
    if (threadIdx.x == 0) any = 0;
    __syncthreads();
    for (int i = threadIdx.x; i < 1024; i += blockDim.x) {
        long long v = ei[i];
        if ((v >> 32) != 0) any = 1;   // benign race
    }
    __syncthreads();
    if (threadIdx.x == 0) g_is64 = (any == 0) ? 1 : 0;
}

// ---------------------------------------------------------------------------
__global__ void init_deg(int n) {
    int i = blockIdx.x * blockDim.x + threadIdx.x;
    if (i < n) g_deg[i] = 1.0f;            // self-loop
}

__global__ void deg_kernel(const void* __restrict__ ei, int E) {
    int e = blockIdx.x * blockDim.x + threadIdx.x;
    if (e >= E) return;
    int d;
    if (g_is64) d = (int)((const long long*)ei)[E + e];
    else        d = ((const int*)ei)[E + e];
    atomicAdd(&g_deg[d], 1.0f);
}

__global__ void dinv_kernel(int n) {
    int i = blockIdx.x * blockDim.x + threadIdx.x;
    if (i < n) {
        float dg = g_deg[i];
        g_dinv[i] = (dg > 0.f) ? rsqrtf(dg) : 0.f;
    }
}

// ---------------------------------------------------------------------------
// B[i,:] = dinv[i]^2 * A[i,:]   (self-loop term; also zero-initializes B)
__global__ void selfloop_init(const float* __restrict__ A, float* __restrict__ B, int n) {
    int t = blockIdx.x * blockDim.x + threadIdx.x;  // one float4 per thread
    if (t >= n * (FH / 4)) return;
    int node = t / (FH / 4);
    float s = g_dinv[node];
    s = s * s;
    float4 v = ((const float4*)A)[t];
    v.x *= s; v.y *= s; v.z *= s; v.w *= s;
    ((float4*)B)[t] = v;
}

// agg[dst,:] += h[src,:] * dinv[src]*dinv[dst]   — 16 lanes per edge, float4 RED
__global__ void scatter_kernel(const void* __restrict__ ei, int E,
                               const float* __restrict__ h, float* __restrict__ agg) {
    int g = blockIdx.x * blockDim.x + threadIdx.x;
    int lane = g & 15;
    int e = g >> 4;
    if (e >= E) return;
    int s, d;
    if (g_is64) {
        const long long* p = (const long long*)ei;
        s = (int)p[e]; d = (int)p[E + e];
    } else {
        const int* p = (const int*)ei;
        s = p[e]; d = p[E + e];
    }
    float norm = g_dinv[s] * g_dinv[d];
    float4 v = ((const float4*)(h + (size_t)s * FH))[lane];
    v.x *= norm; v.y *= norm; v.z *= norm; v.w *= norm;
    atomicAdd((float4*)(agg + (size_t)d * FH) + lane, v);
}

// B = relu(B + bias)  (F=64)
__global__ void bias_relu(float* __restrict__ B, const float* __restrict__ bias, int n) {
    int t = blockIdx.x * blockDim.x + threadIdx.x;
    if (t >= n * (FH / 4)) return;
    int j = (t & (FH / 4 - 1)) * 4;
    float4 v = ((float4*)B)[t];
    v.x = fmaxf(v.x + bias[j + 0], 0.f);
    v.y = fmaxf(v.y + bias[j + 1], 0.f);
    v.z = fmaxf(v.z + bias[j + 2], 0.f);
    v.w = fmaxf(v.w + bias[j + 3], 0.f);
    ((float4*)B)[t] = v;
}

// ---------------------------------------------------------------------------
// Tiled fp32 GEMM: out[n,N] = X[n,K] @ W[K,N] (+bias). 64-row tiles,
// thread-tile 4x4, block (N/4, 16).
template<int K, int N, bool BIAS>
__global__ void gemm_kernel(const float* __restrict__ X, const float* __restrict__ W,
                            const float* __restrict__ bias, float* __restrict__ out, int n) {
    constexpr int TX = N / 4;
    constexpr int NT = TX * 16;
    __shared__ float Xs[64][65];
    __shared__ float Ws[64][N];
    int row0 = blockIdx.x * 64;
    int tx = threadIdx.x, ty = threadIdx.y;
    int tid = ty * TX + tx;
    float acc[4][4] = {};

    for (int k0 = 0; k0 < K; k0 += 64) {
        // X tile: 64 rows x 64 cols (float4 loads, coalesced)
        for (int i = tid; i < 64 * 16; i += NT) {
            int r = i >> 4, c4 = i & 15;
            float4 v = make_float4(0.f, 0.f, 0.f, 0.f);
            int row = row0 + r;
            if (row < n) v = *(const float4*)(X + (size_t)row * K + k0 + c4 * 4);
            Xs[r][c4 * 4 + 0] = v.x; Xs[r][c4 * 4 + 1] = v.y;
            Xs[r][c4 * 4 + 2] = v.z; Xs[r][c4 * 4 + 3] = v.w;
        }
        // W tile: 64 rows x N cols
        for (int i = tid; i < 64 * (N / 4); i += NT) {
            int r = i / (N / 4), c4 = i % (N / 4);
            float4 v = *(const float4*)(W + (size_t)(k0 + r) * N + c4 * 4);
            *(float4*)&Ws[r][c4 * 4] = v;
        }
        __syncthreads();
        #pragma unroll
        for (int k = 0; k < 64; k++) {
            float4 w = *(float4*)&Ws[k][tx * 4];
            #pragma unroll
            for (int i = 0; i < 4; i++) {
                float a = Xs[ty * 4 + i][k];
                acc[i][0] += a * w.x;
                acc[i][1] += a * w.y;
                acc[i][2] += a * w.z;
                acc[i][3] += a * w.w;
            }
        }
        __syncthreads();
    }

    #pragma unroll
    for (int i = 0; i < 4; i++) {
        int row = row0 + ty * 4 + i;
        if (row < n) {
            #pragma unroll
            for (int j = 0; j < 4; j++) {
                float v = acc[i][j];
                if (BIAS) v += bias[tx * 4 + j];
                out[(size_t)row * N + tx * 4 + j] = v;
            }
        }
    }
}

// ---------------------------------------------------------------------------
extern "C" void kernel_launch(void* const* d_in, const int* in_sizes, int n_in,
                              void* d_out, int out_size) {
    const float* x   = (const float*)d_in[0];
    const void*  ei  = d_in[1];
    // d_in[2] = batch (unused)
    const float* W1  = (const float*)d_in[3];
    const float* b1  = (const float*)d_in[4];
    const float* W2  = (const float*)d_in[5];
    const float* b2  = (const float*)d_in[6];
    const float* Wfc = (const float*)d_in[7];
    const float* bfc = (const float*)d_in[8];
    float* out = (float*)d_out;

    int n = in_sizes[0] / 128;   // 100000
    int E = in_sizes[1] / 2;     // 1600000 (element count = 2E for int32 and int64)

    float *A, *B;
    cudaGetSymbolAddress((void**)&A, g_A);
    cudaGetSymbolAddress((void**)&B, g_B);

    int nb_n   = (n + 255) / 256;
    int nb_E   = (E + 255) / 256;
    int nb_el  = (n * (FH / 4) + 255) / 256;       // elementwise over n*64 floats (float4)
    int nb_sc  = (E * 16 + 255) / 256;             // 16 lanes per edge
    int nb_g   = (n + 63) / 64;

    // Degree / normalization
    probe_dtype<<<1, 256>>>((const long long*)ei);
    init_deg<<<nb_n, 256>>>(n);
    deg_kernel<<<nb_E, 256>>>(ei, E);
    dinv_kernel<<<nb_n, 256>>>(n);

    // Layer 1: A = x @ W1 ; B = dinv^2*A + scatter ; B = relu(B + b1)
    gemm_kernel<128, 64, false><<<nb_g, dim3(16, 16)>>>(x, W1, nullptr, A, n);
    selfloop_init<<<nb_el, 256>>>(A, B, n);
    scatter_kernel<<<nb_sc, 256>>>(ei, E, A, B);
    bias_relu<<<nb_el, 256>>>(B, b1, n);

    // Layer 2: A = B @ W2 ; B = dinv^2*A + scatter ; B = relu(B + b2)
    gemm_kernel<64, 64, false><<<nb_g, dim3(16, 16)>>>(B, W2, nullptr, A, n);
    selfloop_init<<<nb_el, 256>>>(A, B, n);
    scatter_kernel<<<nb_sc, 256>>>(ei, E, A, B);
    bias_relu<<<nb_el, 256>>>(B, b2, n);

    // FC: out = B @ Wfc + bfc
    gemm_kernel<64, 32, true><<<nb_g, dim3(8, 16)>>>(B, Wfc, bfc, out, n);
}